// round 5
// baseline (speedup 1.0000x reference)
#include <cuda_runtime.h>
#include <math.h>

#define Bn 4
#define Hn 512
#define Wn 512
#define Sn 40
#define PADc 32
#define OUTW 448
#define NPIX (Hn * Wn)

// ---------------- device scratch ----------------
__device__ float2 g_inc[Bn * NPIX];     // [b][colslot][hslot] permuted k-space
__device__ float2 g_b1[Bn * NPIX];      // [b][h or slot][wslot]
__device__ float2 g_propT[NPIX];        // [colslot][hslot] double-permuted
__device__ float2 g_greenT[NPIX];
__device__ float2 g_finalT[NPIX];
__device__ float2 g_twA[512];           // (cos,sin) of 2*pi*t*br4(s)/512 at [s*32+t]
__device__ float2 g_w32[32];            // (cos,sin) of 2*pi*k/32
__device__ float2 g_sampT[(size_t)Sn * Bn * NPIX];  // [s][b][h][w] natural spatial

__device__ __forceinline__ float2 cadd(float2 a, float2 b) { return make_float2(a.x + b.x, a.y + b.y); }
__device__ __forceinline__ float2 csub(float2 a, float2 b) { return make_float2(a.x - b.x, a.y - b.y); }
__device__ __forceinline__ float2 cmul(float2 a, float2 b) {
    return make_float2(fmaf(a.x, b.x, -a.y * b.y), fmaf(a.x, b.y, a.y * b.x));
}
// multiply a by (w.x + i*S*w.y) : S=-1 forward e^{-i}, S=+1 inverse
template <int S>
__device__ __forceinline__ float2 cmulw(float2 a, float2 w) {
    float wy = (S < 0) ? -w.y : w.y;
    return make_float2(fmaf(w.x, a.x, -wy * a.y), fmaf(w.x, a.y, wy * a.x));
}

__device__ __forceinline__ float2 shflx(float2 a, int m) {
    float2 r;
    r.x = __shfl_xor_sync(0xffffffffu, a.x, m);
    r.y = __shfl_xor_sync(0xffffffffu, a.y, m);
    return r;
}

// ---------------- 16-pt register DFTs ----------------
// DIF: natural input j, output slot s holds k1=br4(s)
template <int S>
__device__ __forceinline__ void dft16_dif(float2* v) {
    const float c1 = 0.9238795325112867f, s1 = 0.3826834323650898f, r = 0.7071067811865476f;
    {   // h=8 (m=16)
        const float wc[8] = {1.f, c1, r, s1, 0.f, -s1, -r, -c1};
        const float ws[8] = {0.f, s1, r, c1, 1.f, c1, r, s1};
#pragma unroll
        for (int j = 0; j < 8; j++) {
            float2 a = v[j], b = v[j + 8];
            v[j] = cadd(a, b);
            v[j + 8] = cmulw<S>(csub(a, b), make_float2(wc[j], ws[j]));
        }
    }
    {   // h=4 (m=8)
        const float wc[4] = {1.f, r, 0.f, -r};
        const float ws[4] = {0.f, r, 1.f, r};
#pragma unroll
        for (int b0 = 0; b0 < 16; b0 += 8)
#pragma unroll
            for (int j = 0; j < 4; j++) {
                float2 a = v[b0 + j], b = v[b0 + j + 4];
                v[b0 + j] = cadd(a, b);
                v[b0 + j + 4] = cmulw<S>(csub(a, b), make_float2(wc[j], ws[j]));
            }
    }
    // h=2 (m=4): j=0 plain, j=1 multiply by i*S
#pragma unroll
    for (int b0 = 0; b0 < 16; b0 += 4) {
        { float2 a = v[b0], b = v[b0 + 2]; v[b0] = cadd(a, b); v[b0 + 2] = csub(a, b); }
        {
            float2 a = v[b0 + 1], b = v[b0 + 3];
            v[b0 + 1] = cadd(a, b);
            float2 d = csub(a, b);
            v[b0 + 3] = (S < 0) ? make_float2(d.y, -d.x) : make_float2(-d.y, d.x);
        }
    }
    // h=1
#pragma unroll
    for (int b0 = 0; b0 < 16; b0 += 2) {
        float2 a = v[b0], b = v[b0 + 1];
        v[b0] = cadd(a, b);
        v[b0 + 1] = csub(a, b);
    }
}

// DIT: input slot s holds C[k1=br4(s)], output natural j
template <int S>
__device__ __forceinline__ void dft16_dit(float2* v) {
    const float c1 = 0.9238795325112867f, s1 = 0.3826834323650898f, r = 0.7071067811865476f;
    // h=1
#pragma unroll
    for (int b0 = 0; b0 < 16; b0 += 2) {
        float2 tt = v[b0 + 1];
        v[b0 + 1] = csub(v[b0], tt);
        v[b0] = cadd(v[b0], tt);
    }
    // h=2 (m=4)
#pragma unroll
    for (int b0 = 0; b0 < 16; b0 += 4) {
        { float2 tt = v[b0 + 2]; v[b0 + 2] = csub(v[b0], tt); v[b0] = cadd(v[b0], tt); }
        {
            float2 w = v[b0 + 3];
            float2 tt = (S < 0) ? make_float2(w.y, -w.x) : make_float2(-w.y, w.x);
            v[b0 + 3] = csub(v[b0 + 1], tt);
            v[b0 + 1] = cadd(v[b0 + 1], tt);
        }
    }
    {   // h=4 (m=8)
        const float wc[4] = {1.f, r, 0.f, -r};
        const float ws[4] = {0.f, r, 1.f, r};
#pragma unroll
        for (int b0 = 0; b0 < 16; b0 += 8)
#pragma unroll
            for (int j = 0; j < 4; j++) {
                float2 tt = cmulw<S>(v[b0 + j + 4], make_float2(wc[j], ws[j]));
                v[b0 + j + 4] = csub(v[b0 + j], tt);
                v[b0 + j] = cadd(v[b0 + j], tt);
            }
    }
    {   // h=8 (m=16)
        const float wc[8] = {1.f, c1, r, s1, 0.f, -s1, -r, -c1};
        const float ws[8] = {0.f, s1, r, c1, 1.f, c1, r, s1};
#pragma unroll
        for (int j = 0; j < 8; j++) {
            float2 tt = cmulw<S>(v[j + 8], make_float2(wc[j], ws[j]));
            v[j + 8] = csub(v[j], tt);
            v[j] = cadd(v[j], tt);
        }
    }
}

// ---------------- cross-lane 32-pt DFTs (per reg) ----------------
// DIF: natural lane in, lane L out holds index br5(L)
template <int S>
__device__ __forceinline__ void x32_dif(float2* v, int t, const float2* wst) {
#pragma unroll
    for (int st = 0; st < 5; st++) {
        const int h = 16 >> st;
        const bool up = (t & h) != 0;
        const float sg = up ? -1.f : 1.f;
#pragma unroll
        for (int r0 = 0; r0 < 16; r0++) {
            float2 p = shflx(v[r0], h);
            float2 e = make_float2(fmaf(sg, v[r0].x, p.x), fmaf(sg, v[r0].y, p.y));
            if (st < 4 && up) e = cmulw<S>(e, wst[st]);
            v[r0] = e;
        }
    }
}

// DIT: lane L in holds index br5(L), natural lane out
template <int S>
__device__ __forceinline__ void x32_dit(float2* v, int t, const float2* wst) {
#pragma unroll
    for (int st = 0; st < 5; st++) {
        const int h = 1 << st;
        const bool up = (t & h) != 0;
        const float sg = up ? -1.f : 1.f;
#pragma unroll
        for (int r0 = 0; r0 < 16; r0++) {
            float2 p = shflx(v[r0], h);
            float2 odd = up ? v[r0] : p;
            float2 evn = up ? p : v[r0];
            float2 m = (st == 0) ? odd : cmulw<S>(odd, wst[4 - st]);
            v[r0] = make_float2(fmaf(sg, m.x, evn.x), fmaf(sg, m.y, evn.y));
        }
    }
}

__device__ __forceinline__ void load_wst(int t, float2* wst) {
    wst[0] = g_w32[t & 15];         // m=32
    wst[1] = g_w32[(t & 7) << 1];   // m=16
    wst[2] = g_w32[(t & 3) << 2];   // m=8
    wst[3] = g_w32[(t & 1) << 3];   // m=4
}

// FFT-A (slot output): dft16 -> twiddle -> cross-lane
template <int S>
__device__ __forceinline__ void fftA(float2* v, int t, const float2* wst) {
    dft16_dif<S>(v);
#pragma unroll
    for (int s = 1; s < 16; s++) v[s] = cmulw<S>(v[s], g_twA[s * 32 + t]);
    x32_dif<S>(v, t, wst);
}
// FFT-B (slot input, natural output): cross-lane -> twiddle -> dft16
template <int S>
__device__ __forceinline__ void fftB(float2* v, int t, const float2* wst) {
    x32_dit<S>(v, t, wst);
#pragma unroll
    for (int s = 1; s < 16; s++) v[s] = cmulw<S>(v[s], g_twA[s * 32 + t]);
    dft16_dit<S>(v);
}

// ---------------- precompute ----------------
__device__ __forceinline__ int br4(int x) {
    return ((x & 1) << 3) | ((x & 2) << 1) | ((x & 4) >> 1) | ((x & 8) >> 3);
}
__device__ __forceinline__ int br5(int x) {
    return ((x & 1) << 4) | ((x & 2) << 2) | (x & 4) | ((x & 8) >> 2) | ((x & 16) >> 4);
}
__device__ __forceinline__ int permK(int i) { return br4(i >> 5) + 16 * br5(i & 31); }

__global__ void k_tables(const float* __restrict__ kz, const float* __restrict__ oabs,
                         const float* __restrict__ gmask, const float* __restrict__ oph) {
    int i = threadIdx.x;   // hslot
    int c = blockIdx.x;    // colslot
    if (c == 0) {
        int s = i >> 5, t = i & 31;
        float th = 6.283185307179586f * (float)(t * br4(s)) * (1.0f / 512.0f);
        float sv, cv;
        sincosf(th, &sv, &cv);
        g_twA[i] = make_float2(cv, sv);
        if (i < 32) {
            float t2 = 6.283185307179586f * (float)i * (1.0f / 32.0f);
            float s2, c2;
            sincosf(t2, &s2, &c2);
            g_w32[i] = make_float2(c2, s2);
        }
    }
    int kh = permK(i), kw = permK(c);
    int src = kh * Wn + kw;
    float k = kz[src];
    float th = k * 0.1f;
    float s, cc;
    sincosf(th, &s, &cc);
    int dst = c * Hn + i;
    g_propT[dst] = make_float2(cc, s);
    float inv2k = 0.5f / k;
    float m = gmask[src];
    g_greenT[dst] = make_float2(-s * inv2k * m, cc * inv2k * m);
    float ph = oph[src] - 5.0f * th;   // conj(prop^25)*prop^20 folded into otf
    float s2, c2;
    sincosf(ph, &s2, &c2);
    float a = oabs[src];
    g_finalT[dst] = make_float2(a * c2, a * s2);
}

// ---------------- sample transpose [B,H,W,S] -> [S,B,H,W] float2 ----------------
__global__ void k_transpose(const float* __restrict__ re, const float* __restrict__ im) {
    __shared__ float2 tile[128 * Sn];
    const int wt = blockIdx.x;
    const int bh = blockIdx.y;
    const int b = bh / Hn, h = bh % Hn;
    const size_t base = ((size_t)bh * Wn + (size_t)wt * 128) * Sn;
    for (int t = threadIdx.x; t < 128 * Sn; t += 256)
        tile[t] = make_float2(re[base + t], im[base + t]);
    __syncthreads();
    for (int t = threadIdx.x; t < 128 * Sn; t += 256) {
        int s = t >> 7;
        int wp = t & 127;
        g_sampT[(((size_t)s * Bn + b) * Hn + h) * Wn + (size_t)wt * 128 + wp] = tile[wp * Sn + s];
    }
}

// ---------------- row kernels: 1 warp = 1 line, no smem, no barriers ----------------
__global__ void __launch_bounds__(128, 8) k_row_init(const float* __restrict__ pre,
                                                     const float* __restrict__ pim) {
    const int t = threadIdx.x & 31;
    const int line = blockIdx.x * 4 + (threadIdx.x >> 5);
    const size_t rb = (size_t)line * Wn;
    float2 wst[4];
    load_wst(t, wst);
    float2 v[16];
#pragma unroll
    for (int j = 0; j < 16; j++) {
        int i = j * 32 + t;
        v[j] = make_float2(pre[rb + i], pim[rb + i]);
    }
    fftA<-1>(v, t, wst);
#pragma unroll
    for (int s = 0; s < 16; s++) g_b1[rb + s * 32 + t] = v[s];
}

__global__ void __launch_bounds__(128, 8) k_row_fused(int slice) {
    const int t = threadIdx.x & 31;
    const int line = blockIdx.x * 4 + (threadIdx.x >> 5);
    const size_t rb = (size_t)line * Wn;
    float2 wst[4];
    load_wst(t, wst);
    float2 v[16];
#pragma unroll
    for (int s = 0; s < 16; s++) v[s] = g_b1[rb + s * 32 + t];
    fftB<+1>(v, t, wst);                       // inverse row FFT -> spatial
    const float sc = 0.1f / (512.0f * 512.0f); // DZ * ifft2 norm
    const size_t sb = (size_t)slice * (Bn * NPIX) + rb;
#pragma unroll
    for (int j = 0; j < 16; j++) {
        float2 sl = g_sampT[sb + j * 32 + t];
        sl.x *= sc;
        sl.y *= sc;
        v[j] = cmul(v[j], sl);
    }
    fftA<-1>(v, t, wst);                       // forward row FFT
#pragma unroll
    for (int s = 0; s < 16; s++) g_b1[rb + s * 32 + t] = v[s];
}

__global__ void __launch_bounds__(128, 8) k_row_final(float* __restrict__ out) {
    const int t = threadIdx.x & 31;
    const int line = blockIdx.x * 4 + (threadIdx.x >> 5);  // 0..B*OUTW-1
    const int b = line / OUTW;
    const int ho = line - b * OUTW;
    const size_t rb = ((size_t)b * Hn + ho + PADc) * Wn;
    float2 wst[4];
    load_wst(t, wst);
    float2 v[16];
#pragma unroll
    for (int s = 0; s < 16; s++) v[s] = g_b1[rb + s * 32 + t];
    fftB<+1>(v, t, wst);
    const float sc = 1.0f / (512.0f * 512.0f);
    const size_t ob = ((size_t)b * OUTW + ho) * OUTW;
#pragma unroll
    for (int j = 1; j < 15; j++) {   // w = 32j + t in [32, 480)
        float2 a = v[j];
        out[ob + (j - 1) * 32 + t] = sqrtf(a.x * a.x + a.y * a.y) * sc;
    }
}

// ---------------- column kernel: 4 warps = 4 columns, 2 barriers ----------------
// MODE 0: inc = fftcol(b1); ifftcol(inc) -> b1
// MODE 1: inc = inc*prop + green*fftcol(b1); ifftcol(inc) -> b1
// MODE 2: ifftcol((inc*prop + green*fftcol(b1)) * final) -> b1 (no inc store)
template <int MODE>
__global__ void __launch_bounds__(128, 8) k_col() {
    __shared__ float2 tile[4 * 514];
    const int tid = threadIdx.x;
    const int w = tid >> 5, t = tid & 31;
    const int cb = blockIdx.x * 4;
    const size_t base = (size_t)blockIdx.y * NPIX;
    float2 wst[4];
    load_wst(t, wst);
#pragma unroll
    for (int it = 0; it < 16; it++) {
        int e = it * 128 + tid;
        int h = e >> 2, c = e & 3;
        tile[c * 514 + h] = g_b1[base + (size_t)h * Wn + cb + c];
    }
    __syncthreads();
    float2* tc = tile + w * 514;
    float2 v[16];
#pragma unroll
    for (int j = 0; j < 16; j++) v[j] = tc[j * 32 + t];
    fftA<-1>(v, t, wst);                      // forward col FFT -> k-space slots
    const int col = cb + w;
    const size_t ib = base + (size_t)col * Hn;
    const int pb = col * Hn;
#pragma unroll
    for (int s = 0; s < 16; s++) {
        int i = s * 32 + t;
        if (MODE == 0) {
            g_inc[ib + i] = v[s];
        } else {
            float2 u = cmul(g_inc[ib + i], g_propT[pb + i]);
            float2 s2 = cmul(g_greenT[pb + i], v[s]);
            float2 ni = cadd(u, s2);
            if (MODE == 1) {
                g_inc[ib + i] = ni;
                v[s] = ni;
            } else {
                v[s] = cmul(ni, g_finalT[pb + i]);
            }
        }
    }
    fftB<+1>(v, t, wst);                      // inverse col FFT -> spatial h
#pragma unroll
    for (int j = 0; j < 16; j++) tc[j * 32 + t] = v[j];
    __syncthreads();
#pragma unroll
    for (int it = 0; it < 16; it++) {
        int e = it * 128 + tid;
        int h = e >> 2, c = e & 3;
        g_b1[base + (size_t)h * Wn + cb + c] = tile[c * 514 + h];
    }
}

// ---------------- launch ----------------
extern "C" void kernel_launch(void* const* d_in, const int* in_sizes, int n_in,
                              void* d_out, int out_size) {
    (void)in_sizes; (void)n_in; (void)out_size;
    const float* sre  = (const float*)d_in[0];
    const float* sim  = (const float*)d_in[1];
    const float* pre  = (const float*)d_in[2];
    const float* pim  = (const float*)d_in[3];
    const float* kz   = (const float*)d_in[4];
    const float* oabs = (const float*)d_in[5];
    const float* gm   = (const float*)d_in[6];
    const float* oph  = (const float*)d_in[7];
    float* out = (float*)d_out;

    k_tables<<<512, 512>>>(kz, oabs, gm, oph);
    k_transpose<<<dim3(Wn / 128, Bn * Hn), 256>>>(sre, sim);

    dim3 colG(Wn / 4, Bn);

    k_row_init<<<Bn * Hn / 4, 128>>>(pre, pim);
    k_col<0><<<colG, 128>>>();

    for (int s = 0; s < Sn; s++) {
        k_row_fused<<<Bn * Hn / 4, 128>>>(s);
        if (s < Sn - 1)
            k_col<1><<<colG, 128>>>();
        else
            k_col<2><<<colG, 128>>>();
    }

    k_row_final<<<Bn * OUTW / 4, 128>>>(out);
}

// round 6
// speedup vs baseline: 1.2286x; 1.2286x over previous
#include <cuda_runtime.h>
#include <math.h>

#define Bn 4
#define Hn 512
#define Wn 512
#define Sn 40
#define PADc 32
#define OUTW 448
#define NPIX (Hn * Wn)

// ---------------- device scratch ----------------
__device__ __align__(16) float2 g_inc[Bn * NPIX];     // [b][col][h]  transposed k-space
__device__ __align__(16) float2 g_b1[Bn * NPIX];      // [b][h][w] row-major staging
__device__ __align__(16) float2 g_propT[NPIX];        // [col][h]
__device__ __align__(16) float2 g_greenT[NPIX];
__device__ __align__(16) float2 g_finalT[NPIX];
__device__ __align__(16) float2 g_tw[512];            // exp(-2*pi*i*m/512)
__device__ __align__(16) float2 g_sampT[(size_t)Sn * Bn * NPIX]; // [s][b][h][w]

__device__ __forceinline__ float2 cadd(float2 a, float2 b) { return make_float2(a.x + b.x, a.y + b.y); }
__device__ __forceinline__ float2 csub(float2 a, float2 b) { return make_float2(a.x - b.x, a.y - b.y); }
__device__ __forceinline__ float2 cmul(float2 a, float2 b) {
    return make_float2(fmaf(a.x, b.x, -a.y * b.y), fmaf(a.x, b.y, a.y * b.x));
}

__device__ __forceinline__ void gbar(int id) {
    asm volatile("bar.sync %0, 64;" :: "r"(id) : "memory");
}

// ---------------- 8-point DFT in registers ----------------
template <int SIGN>
__device__ __forceinline__ void fft8(float2* v) {
    const float s = (float)SIGN;
    const float r = 0.7071067811865476f;
    float2 t0 = cadd(v[0], v[4]), t1 = cadd(v[1], v[5]), t2 = cadd(v[2], v[6]), t3 = cadd(v[3], v[7]);
    float2 t4 = csub(v[0], v[4]), t5 = csub(v[1], v[5]), t6 = csub(v[2], v[6]), t7 = csub(v[3], v[7]);
    t5 = make_float2(r * t5.x - s * r * t5.y, s * r * t5.x + r * t5.y);
    t6 = make_float2(-s * t6.y, s * t6.x);
    t7 = make_float2(-r * t7.x - s * r * t7.y, s * r * t7.x - r * t7.y);
    float2 p0 = cadd(t0, t2), p2 = csub(t0, t2), p1 = cadd(t1, t3), p3 = csub(t1, t3);
    p3 = make_float2(-s * p3.y, s * p3.x);
    float2 q0 = cadd(t4, t6), q2 = csub(t4, t6), q1 = cadd(t5, t7), q3 = csub(t5, t7);
    q3 = make_float2(-s * q3.y, s * q3.x);
    v[0] = cadd(p0, p1); v[4] = csub(p0, p1); v[2] = cadd(p2, p3); v[6] = csub(p2, p3);
    v[1] = cadd(q0, q1); v[5] = csub(q0, q1); v[3] = cadd(q2, q3); v[7] = csub(q2, q3);
}

// ---------------- 512-point FFT: 64 threads, group-scoped named barriers ----------------
// entry: v[n1] = x[n1*64 + t]; exit: v[j2] = X[t + 64*j2]
// ex: per-group region (>=576 float2). barid: named barrier id (1..4), 64 threads.
template <int SIGN>
__device__ __forceinline__ void fft512(float2* v, float2* ex, const float2* tw, int t, int barid) {
    fft8<SIGN>(v);
#pragma unroll
    for (int k = 1; k < 8; k++) {
        float2 w = tw[t * k];
        if (SIGN > 0) w.y = -w.y;
        v[k] = cmul(v[k], w);
    }
    gbar(barid);                        // region free (prior reads done)
#pragma unroll
    for (int k = 0; k < 8; k++) ex[t * 9 + k] = v[k];
    gbar(barid);
    const int m2 = t & 7, k1 = t >> 3;
#pragma unroll
    for (int m1 = 0; m1 < 8; m1++) v[m1] = ex[(m1 * 8 + m2) * 9 + k1];
    fft8<SIGN>(v);
#pragma unroll
    for (int j = 1; j < 8; j++) {
        float2 w = tw[8 * m2 * j];
        if (SIGN > 0) w.y = -w.y;
        v[j] = cmul(v[j], w);
    }
    gbar(barid);
#pragma unroll
    for (int j = 0; j < 8; j++) ex[(j * 8 + m2) * 9 + k1] = v[j];
    gbar(barid);
    const int k1b = t & 7, j1 = t >> 3;
#pragma unroll
    for (int m = 0; m < 8; m++) v[m] = ex[(j1 * 8 + m) * 9 + k1b];
    fft8<SIGN>(v);
}

// ---------------- precompute tables (transposed [col][h]) ----------------
__global__ void k_tables(const float* __restrict__ kz, const float* __restrict__ oabs,
                         const float* __restrict__ gmask, const float* __restrict__ oph) {
    int w = threadIdx.x;   // 0..511
    int h = blockIdx.x;    // 0..511
    if (h == 0) {
        float th = 6.283185307179586f * (float)w * (1.0f / 512.0f);
        float s, c;
        sincosf(th, &s, &c);
        g_tw[w] = make_float2(c, -s);
    }
    int src = h * Wn + w;
    float k = kz[src];
    float th = k * 0.1f;
    float s, cc;
    sincosf(th, &s, &cc);
    int dst = w * Hn + h;              // transposed
    g_propT[dst] = make_float2(cc, s);
    float inv2k = 0.5f / k;
    float m = gmask[src];
    g_greenT[dst] = make_float2(-s * inv2k * m, cc * inv2k * m);
    float ph = oph[src] - 5.0f * th;   // conj(prop^25)*prop^20 folded into otf
    float s2, c2;
    sincosf(ph, &s2, &c2);
    float a = oabs[src];
    g_finalT[dst] = make_float2(a * c2, a * s2);
}

// ---------------- sample transpose [B,H,W,S] -> [S,B,H,W] float2 ----------------
__global__ void k_transpose(const float* __restrict__ re, const float* __restrict__ im) {
    __shared__ float2 tile[128 * Sn];
    const int wt = blockIdx.x;
    const int bh = blockIdx.y;
    const int b = bh / Hn, h = bh % Hn;
    const size_t base = ((size_t)bh * Wn + (size_t)wt * 128) * Sn;
    for (int t = threadIdx.x; t < 128 * Sn; t += 256)
        tile[t] = make_float2(re[base + t], im[base + t]);
    __syncthreads();
    for (int t = threadIdx.x; t < 128 * Sn; t += 256) {
        int s = t >> 7;
        int wp = t & 127;
        g_sampT[(((size_t)s * Bn + b) * Hn + h) * Wn + (size_t)wt * 128 + wp] = tile[wp * Sn + s];
    }
}

// ---------------- cp.async helpers ----------------
__device__ __forceinline__ void cp16(void* sm, const void* gm) {
    unsigned sa = (unsigned)__cvta_generic_to_shared(sm);
    asm volatile("cp.async.cg.shared.global [%0], [%1], 16;" :: "r"(sa), "l"(gm));
}
__device__ __forceinline__ void cp_commit_wait() {
    asm volatile("cp.async.commit_group;");
    asm volatile("cp.async.wait_group 0;");
}

// ---------------- row kernels: block (64,4), 1 group = 1 line ----------------
__global__ void __launch_bounds__(256) k_row_init(const float* __restrict__ pre,
                                                  const float* __restrict__ pim) {
    __shared__ float2 tw[512];
    __shared__ __align__(16) float2 ex[4 * 577];
    const int t = threadIdx.x, ly = threadIdx.y;
    const int flat = ly * 64 + t;
    const int line = blockIdx.x * 4 + ly;
    const size_t rb = (size_t)line * Wn;
    float2 v[8];
#pragma unroll
    for (int n1 = 0; n1 < 8; n1++) {
        int i = n1 * 64 + t;
        v[n1] = make_float2(pre[rb + i], pim[rb + i]);
    }
    for (int i = flat; i < 512; i += 256) tw[i] = g_tw[i];
    __syncthreads();
    fft512<-1>(v, ex + ly * 577, tw, t, ly + 1);
#pragma unroll
    for (int j = 0; j < 8; j++) g_b1[rb + t + 64 * j] = v[j];
}

// ifft-row -> *slab*dz/N^2 -> fft-row
__global__ void __launch_bounds__(256) k_row_fused(int slice) {
    __shared__ float2 tw[512];
    __shared__ __align__(16) float2 ex[4 * 577];
    __shared__ __align__(16) float2 smp[4][512];
    const int t = threadIdx.x, ly = threadIdx.y;
    const int flat = ly * 64 + t;
    const int line = blockIdx.x * 4 + ly;
    const size_t rb = (size_t)line * Wn;
    // prefetch this line's sample slice (DRAM) into smem
    const float2* gs = g_sampT + (size_t)slice * (Bn * NPIX) + rb;
#pragma unroll
    for (int c4 = 0; c4 < 4; c4++)
        cp16(&smp[ly][t * 8 + c4 * 2], gs + t * 8 + c4 * 2);
    asm volatile("cp.async.commit_group;");
    float2 v[8];
#pragma unroll
    for (int n1 = 0; n1 < 8; n1++) v[n1] = g_b1[rb + n1 * 64 + t];
    for (int i = flat; i < 512; i += 256) tw[i] = g_tw[i];
    __syncthreads();
    fft512<+1>(v, ex + ly * 577, tw, t, ly + 1);          // inverse row FFT
    asm volatile("cp.async.wait_group 0;");
    gbar(ly + 1);                                          // cross-thread visibility of smp
    const float sc = 0.1f / (512.0f * 512.0f);             // DZ * ifft2 norm
#pragma unroll
    for (int j = 0; j < 8; j++) {
        float2 sl = smp[ly][t + 64 * j];
        sl.x *= sc;
        sl.y *= sc;
        v[j] = cmul(v[j], sl);
    }
    fft512<-1>(v, ex + ly * 577, tw, t, ly + 1);          // forward row FFT
#pragma unroll
    for (int j = 0; j < 8; j++) g_b1[rb + t + 64 * j] = v[j];
}

// final inverse row + abs + crop
__global__ void __launch_bounds__(256) k_row_final(float* __restrict__ out) {
    __shared__ float2 tw[512];
    __shared__ __align__(16) float2 ex[4 * 577];
    const int t = threadIdx.x, ly = threadIdx.y;
    const int flat = ly * 64 + t;
    const int line = blockIdx.x * 4 + ly;                  // 0..B*OUTW-1
    const int b = line / OUTW;
    const int ho = line - b * OUTW;
    const size_t rb = ((size_t)b * Hn + ho + PADc) * Wn;
    float2 v[8];
#pragma unroll
    for (int n1 = 0; n1 < 8; n1++) v[n1] = g_b1[rb + n1 * 64 + t];
    for (int i = flat; i < 512; i += 256) tw[i] = g_tw[i];
    __syncthreads();
    fft512<+1>(v, ex + ly * 577, tw, t, ly + 1);
    const float sc = 1.0f / (512.0f * 512.0f);
    const size_t ob = ((size_t)b * OUTW + ho) * OUTW;
#pragma unroll
    for (int j = 0; j < 8; j++) {
        int i = t + 64 * j;
        if (i >= PADc && i < Wn - PADc)
            out[ob + i - PADc] = sqrtf(v[j].x * v[j].x + v[j].y * v[j].y) * sc;
    }
}

// ---------------- column kernel: block (64,4) = 4 columns, corner-turn in smem ----------------
// MODE 0: inc = fftcol(b1); ifftcol(inc) -> b1
// MODE 1: inc = inc*prop + green*fftcol(b1); ifftcol(inc) -> b1
// MODE 2: ifftcol((inc*prop + green*fftcol(b1)) * final) -> b1 (no inc store)
template <int MODE>
__global__ void __launch_bounds__(256) k_col() {
    __shared__ float2 tw[512];
    __shared__ __align__(16) float2 tile[4 * 577];        // corner-turn + FFT exchange
    const int t = threadIdx.x, c = threadIdx.y;
    const int flat = c * 64 + t;
    const int cb = blockIdx.x * 4;
    const size_t base = (size_t)blockIdx.y * NPIX;
    // coalesced load of 4 columns into per-column smem regions
#pragma unroll
    for (int it = 0; it < 8; it++) {
        int e = it * 256 + flat;
        int h = e >> 2, cc = e & 3;
        tile[cc * 577 + h] = g_b1[base + (size_t)h * Wn + cb + cc];
    }
    for (int i = flat; i < 512; i += 256) tw[i] = g_tw[i];
    __syncthreads();
    float2 v[8];
#pragma unroll
    for (int n1 = 0; n1 < 8; n1++) v[n1] = tile[c * 577 + n1 * 64 + t];
    fft512<-1>(v, tile + c * 577, tw, t, c + 1);          // forward col FFT
    const int col = cb + c;
    const size_t ib = base + (size_t)col * Hn;
    const int pb = col * Hn;
#pragma unroll
    for (int j = 0; j < 8; j++) {
        int i = t + 64 * j;
        if (MODE == 0) {
            g_inc[ib + i] = v[j];
        } else {
            float2 u = cmul(g_inc[ib + i], g_propT[pb + i]);
            float2 s2 = cmul(g_greenT[pb + i], v[j]);
            float2 ni = cadd(u, s2);
            if (MODE == 1) {
                g_inc[ib + i] = ni;
                v[j] = ni;
            } else {
                v[j] = cmul(ni, g_finalT[pb + i]);
            }
        }
    }
    fft512<+1>(v, tile + c * 577, tw, t, c + 1);          // inverse col FFT
    gbar(c + 1);
#pragma unroll
    for (int j = 0; j < 8; j++) tile[c * 577 + t + 64 * j] = v[j];
    __syncthreads();
#pragma unroll
    for (int it = 0; it < 8; it++) {
        int e = it * 256 + flat;
        int h = e >> 2, cc = e & 3;
        g_b1[base + (size_t)h * Wn + cb + cc] = tile[cc * 577 + h];
    }
}

// ---------------- launch ----------------
extern "C" void kernel_launch(void* const* d_in, const int* in_sizes, int n_in,
                              void* d_out, int out_size) {
    (void)in_sizes; (void)n_in; (void)out_size;
    const float* sre  = (const float*)d_in[0];
    const float* sim  = (const float*)d_in[1];
    const float* pre  = (const float*)d_in[2];
    const float* pim  = (const float*)d_in[3];
    const float* kz   = (const float*)d_in[4];
    const float* oabs = (const float*)d_in[5];
    const float* gm   = (const float*)d_in[6];
    const float* oph  = (const float*)d_in[7];
    float* out = (float*)d_out;

    k_tables<<<512, 512>>>(kz, oabs, gm, oph);
    k_transpose<<<dim3(Wn / 128, Bn * Hn), 256>>>(sre, sim);

    dim3 blk(64, 4);
    dim3 colG(Wn / 4, Bn);

    k_row_init<<<Bn * Hn / 4, blk>>>(pre, pim);
    k_col<0><<<colG, blk>>>();

    for (int s = 0; s < Sn; s++) {
        k_row_fused<<<Bn * Hn / 4, blk>>>(s);
        if (s < Sn - 1)
            k_col<1><<<colG, blk>>>();
        else
            k_col<2><<<colG, blk>>>();
    }

    k_row_final<<<Bn * OUTW / 4, blk>>>(out);
}

// round 7
// speedup vs baseline: 1.5589x; 1.2689x over previous
#include <cuda_runtime.h>
#include <math.h>

#define Bn 4
#define Hn 512
#define Wn 512
#define Sn 40
#define PADc 32
#define OUTW 448
#define NPIX (Hn * Wn)

// ---------------- device scratch ----------------
__device__ __align__(16) float2 g_inc[Bn * NPIX];
__device__ __align__(16) float2 g_b1[Bn * NPIX];
__device__ __align__(16) float2 g_prop[NPIX];
__device__ __align__(16) float2 g_green[NPIX];
__device__ __align__(16) float2 g_final[NPIX];
__device__ __align__(16) float2 g_tw[512];            // exp(-2*pi*i*m/512)
__device__ __align__(16) float2 g_sampT[(size_t)Sn * Bn * NPIX]; // [s][b][h][w]

__device__ __forceinline__ float2 cadd(float2 a, float2 b) { return make_float2(a.x + b.x, a.y + b.y); }
__device__ __forceinline__ float2 csub(float2 a, float2 b) { return make_float2(a.x - b.x, a.y - b.y); }
__device__ __forceinline__ float2 cmul(float2 a, float2 b) {
    return make_float2(fmaf(a.x, b.x, -a.y * b.y), fmaf(a.x, b.y, a.y * b.x));
}

__device__ __forceinline__ void gbar(int id) {
    asm volatile("bar.sync %0, 64;" :: "r"(id) : "memory");
}

// ---------------- 8-point DFT in registers ----------------
template <int SIGN>
__device__ __forceinline__ void fft8(float2* v) {
    const float s = (float)SIGN;
    const float r = 0.7071067811865476f;
    float2 t0 = cadd(v[0], v[4]), t1 = cadd(v[1], v[5]), t2 = cadd(v[2], v[6]), t3 = cadd(v[3], v[7]);
    float2 t4 = csub(v[0], v[4]), t5 = csub(v[1], v[5]), t6 = csub(v[2], v[6]), t7 = csub(v[3], v[7]);
    t5 = make_float2(r * t5.x - s * r * t5.y, s * r * t5.x + r * t5.y);
    t6 = make_float2(-s * t6.y, s * t6.x);
    t7 = make_float2(-r * t7.x - s * r * t7.y, s * r * t7.x - r * t7.y);
    float2 p0 = cadd(t0, t2), p2 = csub(t0, t2), p1 = cadd(t1, t3), p3 = csub(t1, t3);
    p3 = make_float2(-s * p3.y, s * p3.x);
    float2 q0 = cadd(t4, t6), q2 = csub(t4, t6), q1 = cadd(t5, t7), q3 = csub(t5, t7);
    q3 = make_float2(-s * q3.y, s * q3.x);
    v[0] = cadd(p0, p1); v[4] = csub(p0, p1); v[2] = cadd(p2, p3); v[6] = csub(p2, p3);
    v[1] = cadd(q0, q1); v[5] = csub(q0, q1); v[3] = cadd(q2, q3); v[7] = csub(q2, q3);
}

// ---------------- 512-point FFT, double-buffered exchange: 2 barriers total ----------
// entry: v[n1] = x[n1*64 + t]; exit: v[j2] = X[t + 64*j2]
// e0/e1: two distinct per-FFT exchange regions (>=577 float2 each).
// Safety: a buffer is only overwritten after the barrier that retired all its reads;
// strict e0,e1 alternation across consecutive calls keeps this invariant.
template <int SIGN, bool NAMED>
__device__ __forceinline__ void fft512_db(float2* v, float2* e0, float2* e1,
                                          const float2* tw, int t, int barid) {
    fft8<SIGN>(v);
#pragma unroll
    for (int k = 1; k < 8; k++) {
        float2 w = tw[t * k];
        if (SIGN > 0) w.y = -w.y;
        v[k] = cmul(v[k], w);
    }
#pragma unroll
    for (int k = 0; k < 8; k++) e0[t * 9 + k] = v[k];
    if (NAMED) gbar(barid); else __syncthreads();
    const int m2 = t & 7, k1 = t >> 3;
#pragma unroll
    for (int m1 = 0; m1 < 8; m1++) v[m1] = e0[(m1 * 8 + m2) * 9 + k1];
    fft8<SIGN>(v);
#pragma unroll
    for (int j = 1; j < 8; j++) {
        float2 w = tw[8 * m2 * j];
        if (SIGN > 0) w.y = -w.y;
        v[j] = cmul(v[j], w);
    }
#pragma unroll
    for (int j = 0; j < 8; j++) e1[(j * 8 + m2) * 9 + k1] = v[j];
    if (NAMED) gbar(barid); else __syncthreads();
    const int k1b = t & 7, j1 = t >> 3;
#pragma unroll
    for (int m = 0; m < 8; m++) v[m] = e1[(j1 * 8 + m) * 9 + k1b];
    fft8<SIGN>(v);
}

// ---------------- precompute ----------------
__global__ void k_tables(const float* __restrict__ kz, const float* __restrict__ oabs,
                         const float* __restrict__ gmask, const float* __restrict__ oph) {
    int w = threadIdx.x, h = blockIdx.x;
    if (h == 0) {
        float th = 6.283185307179586f * (float)w * (1.0f / 512.0f);
        float s, c;
        sincosf(th, &s, &c);
        g_tw[w] = make_float2(c, -s);
    }
    int idx = h * Wn + w;
    float k = kz[idx];
    float th = k * 0.1f;
    float s, cc;
    sincosf(th, &s, &cc);
    g_prop[idx] = make_float2(cc, s);
    float inv2k = 0.5f / k;
    float m = gmask[idx];
    g_green[idx] = make_float2(-s * inv2k * m, cc * inv2k * m);
    float ph = oph[idx] - 5.0f * th;   // conj(prop^25)*prop^20 folded into otf
    float s2, c2;
    sincosf(ph, &s2, &c2);
    float a = oabs[idx];
    g_final[idx] = make_float2(a * c2, a * s2);
}

// ---------------- sample transpose [B,H,W,S] -> [S,B,H,W] float2 ----------------
__global__ void k_transpose(const float* __restrict__ re, const float* __restrict__ im) {
    __shared__ float2 tile[128 * Sn];
    const int wt = blockIdx.x;
    const int bh = blockIdx.y;
    const int b = bh / Hn, h = bh % Hn;
    const size_t base = ((size_t)bh * Wn + (size_t)wt * 128) * Sn;
    for (int t = threadIdx.x; t < 128 * Sn; t += 256)
        tile[t] = make_float2(re[base + t], im[base + t]);
    __syncthreads();
    for (int t = threadIdx.x; t < 128 * Sn; t += 256) {
        int s = t >> 7;
        int wp = t & 127;
        g_sampT[(((size_t)s * Bn + b) * Hn + h) * Wn + (size_t)wt * 128 + wp] = tile[wp * Sn + s];
    }
}

// ---------------- row kernels: block (64,4), group = contiguous 2 warps ----------------
__global__ void __launch_bounds__(256) k_row_init(const float* __restrict__ pre,
                                                  const float* __restrict__ pim) {
    __shared__ float2 tw[512];
    __shared__ __align__(16) float2 ex[4][2][577];
    const int t = threadIdx.x, ly = threadIdx.y;
    const int line = blockIdx.x * 4 + ly;
    const size_t rb = (size_t)line * Wn;
    float2 v[8];
#pragma unroll
    for (int n1 = 0; n1 < 8; n1++) {
        int i = n1 * 64 + t;
        v[n1] = make_float2(pre[rb + i], pim[rb + i]);
    }
    for (int i = ly * 64 + t; i < 512; i += 256) tw[i] = g_tw[i];
    __syncthreads();
    fft512_db<-1, true>(v, ex[ly][0], ex[ly][1], tw, t, ly + 1);
#pragma unroll
    for (int j = 0; j < 8; j++) g_b1[rb + t + 64 * j] = v[j];
}

// ifft-row -> *slab*dz/N^2 -> fft-row; sample prefetched to registers up front
__global__ void __launch_bounds__(256) k_row_fused(int slice) {
    __shared__ float2 tw[512];
    __shared__ __align__(16) float2 ex[4][2][577];
    const int t = threadIdx.x, ly = threadIdx.y;
    const int line = blockIdx.x * 4 + ly;
    const size_t rb = (size_t)line * Wn;
    float2 v[8], sl[8];
    const float2* gs = g_sampT + (size_t)slice * (Bn * NPIX) + rb;
#pragma unroll
    for (int j = 0; j < 8; j++) sl[j] = gs[t + 64 * j];     // DRAM, hidden behind FFT #1
#pragma unroll
    for (int n1 = 0; n1 < 8; n1++) v[n1] = g_b1[rb + n1 * 64 + t];
    for (int i = ly * 64 + t; i < 512; i += 256) tw[i] = g_tw[i];
    __syncthreads();
    fft512_db<+1, true>(v, ex[ly][0], ex[ly][1], tw, t, ly + 1); // inverse row FFT
    const float sc = 0.1f / (512.0f * 512.0f);                   // DZ * ifft2 norm
#pragma unroll
    for (int j = 0; j < 8; j++) {
        sl[j].x *= sc;
        sl[j].y *= sc;
        v[j] = cmul(v[j], sl[j]);
    }
    fft512_db<-1, true>(v, ex[ly][0], ex[ly][1], tw, t, ly + 1); // forward row FFT
#pragma unroll
    for (int j = 0; j < 8; j++) g_b1[rb + t + 64 * j] = v[j];
}

// final inverse row + abs + crop
__global__ void __launch_bounds__(256) k_row_final(float* __restrict__ out) {
    __shared__ float2 tw[512];
    __shared__ __align__(16) float2 ex[4][2][577];
    const int t = threadIdx.x, ly = threadIdx.y;
    const int line = blockIdx.x * 4 + ly;                   // 0..B*OUTW-1
    const int b = line / OUTW;
    const int ho = line - b * OUTW;
    const size_t rb = ((size_t)b * Hn + ho + PADc) * Wn;
    float2 v[8];
#pragma unroll
    for (int n1 = 0; n1 < 8; n1++) v[n1] = g_b1[rb + n1 * 64 + t];
    for (int i = ly * 64 + t; i < 512; i += 256) tw[i] = g_tw[i];
    __syncthreads();
    fft512_db<+1, true>(v, ex[ly][0], ex[ly][1], tw, t, ly + 1);
    const float sc = 1.0f / (512.0f * 512.0f);
    const size_t ob = ((size_t)b * OUTW + ho) * OUTW;
#pragma unroll
    for (int j = 0; j < 8; j++) {
        int i = t + 64 * j;
        if (i >= PADc && i < Wn - PADc)
            out[ob + i - PADc] = sqrtf(v[j].x * v[j].x + v[j].y * v[j].y) * sc;
    }
}

// ---------------- column kernel: block (8,64), 8 cols, R2 layout, dbl-buffered ----------
// MODE 0: inc = fftcol(b1); ifftcol(inc) -> b1
// MODE 1: inc = inc*prop + green*fftcol(b1); ifftcol(inc) -> b1
// MODE 2: ifftcol((inc*prop + green*fftcol(b1)) * final) -> b1 (no inc store)
// dynamic smem: tw[512] | per-col {e0[577], e1[577]} x 8
template <int MODE>
__global__ void __launch_bounds__(512) k_col() {
    extern __shared__ __align__(16) float2 dsm[];
    float2* tw = dsm;
    const int c = threadIdx.x;     // 0..7
    const int ty = threadIdx.y;    // 0..63
    const int flat = ty * 8 + c;
    const int col = blockIdx.x * 8 + c;
    const size_t base = (size_t)blockIdx.y * NPIX;
    float2* e0 = dsm + 512 + c * 1154;
    float2* e1 = e0 + 577;
    float2 v[8];
#pragma unroll
    for (int n1 = 0; n1 < 8; n1++) v[n1] = g_b1[base + (size_t)(n1 * 64 + ty) * Wn + col];
    tw[flat] = g_tw[flat];
    __syncthreads();
    fft512_db<-1, false>(v, e0, e1, tw, ty, 0);   // forward col FFT
#pragma unroll
    for (int j = 0; j < 8; j++) {
        int r = ty + 64 * j;
        size_t gi = base + (size_t)r * Wn + col;
        int hw = r * Wn + col;
        if (MODE == 0) {
            g_inc[gi] = v[j];
        } else {
            float2 u = cmul(g_inc[gi], g_prop[hw]);
            float2 s2 = cmul(g_green[hw], v[j]);
            float2 ni = cadd(u, s2);
            if (MODE == 1) {
                g_inc[gi] = ni;
                v[j] = ni;
            } else {
                v[j] = cmul(ni, g_final[hw]);
            }
        }
    }
    fft512_db<+1, false>(v, e0, e1, tw, ty, 0);   // inverse col FFT
#pragma unroll
    for (int j = 0; j < 8; j++) g_b1[base + (size_t)(ty + 64 * j) * Wn + col] = v[j];
}

// ---------------- launch ----------------
extern "C" void kernel_launch(void* const* d_in, const int* in_sizes, int n_in,
                              void* d_out, int out_size) {
    (void)in_sizes; (void)n_in; (void)out_size;
    const float* sre  = (const float*)d_in[0];
    const float* sim  = (const float*)d_in[1];
    const float* pre  = (const float*)d_in[2];
    const float* pim  = (const float*)d_in[3];
    const float* kz   = (const float*)d_in[4];
    const float* oabs = (const float*)d_in[5];
    const float* gm   = (const float*)d_in[6];
    const float* oph  = (const float*)d_in[7];
    float* out = (float*)d_out;

    const int colSmem = (512 + 8 * 2 * 577) * (int)sizeof(float2);  // 77,952 B
    cudaFuncSetAttribute(k_col<0>, cudaFuncAttributeMaxDynamicSharedMemorySize, colSmem);
    cudaFuncSetAttribute(k_col<1>, cudaFuncAttributeMaxDynamicSharedMemorySize, colSmem);
    cudaFuncSetAttribute(k_col<2>, cudaFuncAttributeMaxDynamicSharedMemorySize, colSmem);

    k_tables<<<512, 512>>>(kz, oabs, gm, oph);
    k_transpose<<<dim3(Wn / 128, Bn * Hn), 256>>>(sre, sim);

    dim3 rowB(64, 4);
    dim3 colG(Wn / 8, Bn), colB(8, 64);

    k_row_init<<<Bn * Hn / 4, rowB>>>(pre, pim);
    k_col<0><<<colG, colB, colSmem>>>();

    for (int s = 0; s < Sn; s++) {
        k_row_fused<<<Bn * Hn / 4, rowB>>>(s);
        if (s < Sn - 1)
            k_col<1><<<colG, colB, colSmem>>>();
        else
            k_col<2><<<colG, colB, colSmem>>>();
    }

    k_row_final<<<Bn * OUTW / 4, rowB>>>(out);
}